// round 11
// baseline (speedup 1.0000x reference)
#include <cuda_runtime.h>
#include <cuda_fp16.h>
#include <cstdint>

#define B_ 2
#define S_ 2048
#define D_ 1024
#define H_ 16
#define HD_ 64

#define NELEM ((size_t)B_ * S_ * D_)

// ---------------- scratch (allocation-free contract) ----------------
__device__ __half g_wt[4 * D_ * D_];        // W^T [n][k] fp16
__device__ __half g_q16[NELEM], g_k16[NELEM], g_v16[NELEM];
__device__ __half g_ctx[NELEM];
__device__ __half g_ps[(size_t)B_ * H_ * S_ * S_];   // p~ tiles (unnormalized exp2 scores)
__device__ float  g_inv[(size_t)B_ * H_ * 16 * 128]; // per (bh,rb,row): 1/sum

// ---------------- baseline-PTX helpers ----------------
__device__ __forceinline__ uint32_t smem_u32(const void* p) {
    uint32_t a;
    asm("{ .reg .u64 t; cvta.to.shared.u64 t, %1; cvt.u32.u64 %0, t; }" : "=r"(a) : "l"(p));
    return a;
}
__device__ __forceinline__ float ex2f(float x) {
    float y;
    asm("ex2.approx.ftz.f32 %0, %1;" : "=f"(y) : "f"(x));
    return y;
}
#define CP_ASYNC16(dst, src) \
    asm volatile("cp.async.cg.shared.global [%0], [%1], 16;" :: "r"(dst), "l"(src))
#define CP_COMMIT() asm volatile("cp.async.commit_group;" ::: "memory")
#define CP_WAIT1()  asm volatile("cp.async.wait_group 1;" ::: "memory")
#define CP_WAIT0()  asm volatile("cp.async.wait_group 0;" ::: "memory")

#define LDMX4(r, a) \
    asm volatile("ldmatrix.sync.aligned.m8n8.x4.shared.b16 {%0,%1,%2,%3}, [%4];" \
        : "=r"((r)[0]), "=r"((r)[1]), "=r"((r)[2]), "=r"((r)[3]) : "r"(a))
#define LDMX4T(r, a) \
    asm volatile("ldmatrix.sync.aligned.m8n8.x4.trans.shared.b16 {%0,%1,%2,%3}, [%4];" \
        : "=r"((r)[0]), "=r"((r)[1]), "=r"((r)[2]), "=r"((r)[3]) : "r"(a))

#define MMA_F16(d, a, b) \
    asm volatile("mma.sync.aligned.m16n8k16.row.col.f32.f16.f16.f32 " \
        "{%0,%1,%2,%3},{%4,%5,%6,%7},{%8,%9},{%0,%1,%2,%3};" \
        : "+f"((d)[0]), "+f"((d)[1]), "+f"((d)[2]), "+f"((d)[3]) \
        : "r"((a)[0]), "r"((a)[1]), "r"((a)[2]), "r"((a)[3]), "r"((b)[0]), "r"((b)[1]))

// ---------------- weight transpose -> fp16: W[k][n] -> Wt[n][k] ----------------
__global__ __launch_bounds__(256) void wtrans_kernel(
    const float* __restrict__ W0, const float* __restrict__ W1,
    const float* __restrict__ W2, const float* __restrict__ W3,
    __half* __restrict__ th)
{
    __shared__ float t[32][33];
    const int tx = threadIdx.x, ty = threadIdx.y;
    const int n0 = blockIdx.x * 32, k0 = blockIdx.y * 32;
    const int z = blockIdx.z;
    const float* W = z == 0 ? W0 : (z == 1 ? W1 : (z == 2 ? W2 : W3));
    __half* dst = th + (size_t)z * D_ * D_;
#pragma unroll
    for (int j = 0; j < 4; j++)
        t[ty + j * 8][tx] = W[(size_t)(k0 + ty + j * 8) * D_ + n0 + tx];
    __syncthreads();
#pragma unroll
    for (int j = 0; j < 4; j++)
        dst[(size_t)(n0 + ty + j * 8) * D_ + k0 + tx] = __float2half_rn(t[tx][ty + j * 8]);
}

// ---------------- projection GEMM (fp16 single-MMA) ----------------
// AFP32: A is fp32 in gmem, converted to fp16 in the produce stage (fused cast).
template <bool AFP32, bool OUT16>
__global__ __launch_bounds__(256, 2) void gemm_proj(
    const float* __restrict__ Af0, const float* __restrict__ Af1, const float* __restrict__ Af2,
    const __half* __restrict__ Ah,
    const __half* __restrict__ Wt,
    const float* __restrict__ b0, const float* __restrict__ b1, const float* __restrict__ b2,
    float* __restrict__ Cf,
    __half* __restrict__ C0, __half* __restrict__ C1, __half* __restrict__ C2,
    float scale0)
{
    extern __shared__ char smem[];
    constexpr uint32_t A_STAGE = 128 * 80;
    constexpr uint32_t B_BASE = 2 * A_STAGE;
    const uint32_t sbase = smem_u32(smem);

    const int tid = threadIdx.x;
    const int wid = tid >> 5, lane = tid & 31;
    const int wm0 = (wid >> 2) * 64;
    const int wn0 = (wid & 3) * 32;
    const int row0 = blockIdx.y * 128, col0 = blockIdx.x * 128;

    const int z = blockIdx.z;
    const float* Af = z == 0 ? Af0 : (z == 1 ? Af1 : Af2);
    const float* bias = z == 0 ? b0 : (z == 1 ? b1 : b2);
    __half* C16 = z == 0 ? C0 : (z == 1 ? C1 : C2);
    const float scale = z == 0 ? scale0 : 1.0f;
    const __half* W = Wt + (size_t)z * D_ * D_;

    float acc[4][4][4];
#pragma unroll
    for (int im = 0; im < 4; im++)
#pragma unroll
        for (int in_ = 0; in_ < 4; in_++)
#pragma unroll
            for (int j = 0; j < 4; j++) acc[im][in_][j] = 0.0f;

    auto produce = [&](int i) {
        const int st = i & 1;
        const int k0 = i << 5;
        if (AFP32) {
#pragma unroll
            for (int c = tid; c < 512; c += 256) {
                int r = c >> 2, kc = c & 3;
                const float* s = Af + (long long)(row0 + r) * D_ + k0 + kc * 8;
                float4 u0 = *reinterpret_cast<const float4*>(s);
                float4 u1 = *reinterpret_cast<const float4*>(s + 4);
                alignas(16) __half hh[8];
                hh[0] = __float2half_rn(u0.x); hh[1] = __float2half_rn(u0.y);
                hh[2] = __float2half_rn(u0.z); hh[3] = __float2half_rn(u0.w);
                hh[4] = __float2half_rn(u1.x); hh[5] = __float2half_rn(u1.y);
                hh[6] = __float2half_rn(u1.z); hh[7] = __float2half_rn(u1.w);
                *reinterpret_cast<uint4*>(smem + st * A_STAGE + (uint32_t)(r * 80 + kc * 16)) =
                    *reinterpret_cast<uint4*>(hh);
            }
        } else {
#pragma unroll
            for (int c = tid; c < 512; c += 256) {
                int r = c >> 2, kc = c & 3;
                CP_ASYNC16(sbase + st * A_STAGE + (uint32_t)(r * 80 + kc * 16),
                           Ah + (long long)(row0 + r) * D_ + k0 + kc * 8);
            }
        }
#pragma unroll
        for (int c = tid; c < 512; c += 256) {
            int r = c >> 2, kc = c & 3;
            CP_ASYNC16(sbase + B_BASE + st * A_STAGE + (uint32_t)(r * 80 + kc * 16),
                       W + (long long)(col0 + r) * D_ + k0 + kc * 8);
        }
        CP_COMMIT();
    };

    auto compute = [&](int st) {
        const uint32_t bA = sbase + st * A_STAGE;
        const uint32_t bB = sbase + B_BASE + st * A_STAGE;
#pragma unroll
        for (int k2 = 0; k2 < 2; k2++) {
            uint32_t ah[4][4];
            const uint32_t ao = (uint32_t)((wm0 + (lane & 15)) * 80 +
                                           (k2 * 16 + (lane >> 4) * 8) * 2);
#pragma unroll
            for (int im = 0; im < 4; im++)
                LDMX4(ah[im], bA + ao + im * (16 * 80));
            const uint32_t bo = (uint32_t)((wn0 + (lane >> 4) * 8 + (lane & 7)) * 80 +
                                           k2 * 32 + ((lane >> 3) & 1) * 16);
#pragma unroll
            for (int in_ = 0; in_ < 4; in_ += 2) {
                uint32_t bh4[4];
                LDMX4(bh4, bo + bB + in_ * (8 * 80));
#pragma unroll
                for (int im = 0; im < 4; im++) {
                    MMA_F16(acc[im][in_], ah[im], bh4);
                    MMA_F16(acc[im][in_ + 1], ah[im], bh4 + 2);
                }
            }
        }
    };

    const int NS = D_ >> 5;
    produce(0);
    produce(1);
    for (int i = 0; i < NS; i++) {
        if (i + 1 < NS) { CP_WAIT1(); } else { CP_WAIT0(); }
        __syncthreads();
        compute(i & 1);
        __syncthreads();
        if (i + 2 < NS) produce(i + 2);
    }

    const int qrow = lane >> 2;
    const int qcol = (lane & 3) * 2;
#pragma unroll
    for (int im = 0; im < 4; im++) {
#pragma unroll
        for (int half_ = 0; half_ < 2; half_++) {
            const int m = row0 + wm0 + im * 16 + qrow + half_ * 8;
#pragma unroll
            for (int in_ = 0; in_ < 4; in_++) {
                const int n = col0 + wn0 + in_ * 8 + qcol;
                float v0 = (acc[im][in_][half_ * 2 + 0] + bias[n])     * scale;
                float v1 = (acc[im][in_][half_ * 2 + 1] + bias[n + 1]) * scale;
                const long long o = (long long)m * D_ + n;
                if (OUT16) {
                    __half2 hp = __floats2half2_rn(v0, v1);
                    *reinterpret_cast<uint32_t*>(C16 + o) = *reinterpret_cast<uint32_t*>(&hp);
                } else {
                    *reinterpret_cast<float2*>(Cf + o) = make_float2(v0, v1);
                }
            }
        }
    }
}

// ---------------- fused attention: scores + exp2 (no max-shift) + PV ----------------
// grid (rb=S/128, bh=B*H). 8 warps; warp w owns q-rows [w*16, w*16+16).
// q16 pre-scaled by 0.125*log2(e). V consumed in natural [s, hd] layout
// via ldmatrix.trans (no vtrans kernel).
// smem: QS 128x144 | KS 2x128x144 | VS 2x128x144 | PS 128x272 | INVS 128 f32
__global__ __launch_bounds__(256, 1) void attn_fused(
    const __half* __restrict__ q16, const __half* __restrict__ k16,
    const __half* __restrict__ v16,
    __half* __restrict__ pscr, float* __restrict__ invg,
    __half* __restrict__ ctx)
{
    extern __shared__ char sm[];
    const uint32_t sb = smem_u32(sm);
    constexpr uint32_t QS = 0;
    constexpr uint32_t KS = 18432;
    constexpr uint32_t VS = 18432 + 36864;           // 55296
    constexpr uint32_t PS = 55296 + 36864;           // 92160
    constexpr uint32_t INVS = 92160 + 34816;         // 126976: 128 float
    const int tid = threadIdx.x, w = tid >> 5, lane = tid & 31;
    const int rb = blockIdx.x, bh = blockIdx.y, b = bh >> 4, h = bh & 15;
    const int lr = lane >> 2, lc = lane & 3;
    const int row0 = w * 16 + lr;

    // q tile (group 0)
    {
        const __half* src = q16 + ((size_t)b * S_ + (size_t)rb * 128) * D_ + h * 64;
        for (int c = tid; c < 1024; c += 256) {
            int r = c >> 3, ch = c & 7;
            CP_ASYNC16(sb + QS + r * 144 + ch * 16, src + (size_t)r * D_ + ch * 8);
        }
        CP_COMMIT();
    }
    auto produce = [&](int i) {
        int st = i & 1;
        const __half* ks = k16 + ((size_t)b * S_ + (size_t)i * 128) * D_ + h * 64;
        const __half* vs = v16 + ((size_t)b * S_ + (size_t)i * 128) * D_ + h * 64;
        for (int c = tid; c < 1024; c += 256) {
            int r = c >> 3, ch = c & 7;
            CP_ASYNC16(sb + KS + st * 18432 + r * 144 + ch * 16, ks + (size_t)r * D_ + ch * 8);
            CP_ASYNC16(sb + VS + st * 18432 + r * 144 + ch * 16, vs + (size_t)r * D_ + ch * 8);
        }
        CP_COMMIT();
    };
    produce(0);
    produce(1);

    uint32_t qa[4][4];
    float ctxa[8][4];
#pragma unroll
    for (int f8 = 0; f8 < 8; f8++)
#pragma unroll
        for (int j = 0; j < 4; j++) ctxa[f8][j] = 0.0f;
    float sum0 = 0.0f, sum1 = 0.0f;

    for (int i = 0; i < 16; i++) {
        if (i + 1 < 16) { CP_WAIT1(); } else { CP_WAIT0(); }
        __syncthreads();
        if (i == 0) {
#pragma unroll
            for (int kc = 0; kc < 4; kc++)
                LDMX4(qa[kc], sb + QS + (w * 16 + (lane & 15)) * 144 +
                              (kc * 16 + (lane >> 4) * 8) * 2);
        }
        const uint32_t kbuf = sb + KS + (i & 1) * 18432;
        const uint32_t vbuf = sb + VS + (i & 1) * 18432;

        // s = q @ k^T (exp2 domain)
        float sa[16][4];
#pragma unroll
        for (int f = 0; f < 16; f++) {
            sa[f][0] = sa[f][1] = sa[f][2] = sa[f][3] = 0.0f;
        }
#pragma unroll
        for (int kc = 0; kc < 4; kc++) {
            const uint32_t ko = kbuf + ((lane >> 4) * 8 + (lane & 7)) * 144 +
                                kc * 32 + ((lane >> 3) & 1) * 16;
#pragma unroll
            for (int f = 0; f < 16; f += 2) {
                uint32_t kb4[4];
                LDMX4(kb4, ko + f * (8 * 144));
                MMA_F16(sa[f],     qa[kc], kb4);
                MMA_F16(sa[f + 1], qa[kc], kb4 + 2);
            }
        }

        // p~ = exp2(s), per-thread partial sums, fp16 pack (no max shift)
        uint32_t ph0[16], ph1[16];
#pragma unroll
        for (int f = 0; f < 16; f++) {
            float p0 = ex2f(sa[f][0]), p1 = ex2f(sa[f][1]);
            float p2 = ex2f(sa[f][2]), p3 = ex2f(sa[f][3]);
            sum0 += p0 + p1; sum1 += p2 + p3;
            __half2 h01 = __floats2half2_rn(p0, p1);
            __half2 h23 = __floats2half2_rn(p2, p3);
            ph0[f] = *reinterpret_cast<uint32_t*>(&h01);
            ph1[f] = *reinterpret_cast<uint32_t*>(&h23);
        }

        // ctx += p~ @ v   (V in [s, hd] layout; ldmatrix.trans B-frags)
#pragma unroll
        for (int ks2 = 0; ks2 < 8; ks2++) {
            uint32_t pa[4] = { ph0[2 * ks2], ph1[2 * ks2],
                               ph0[2 * ks2 + 1], ph1[2 * ks2 + 1] };
            const uint32_t vo = vbuf +
                (ks2 * 16 + ((lane >> 3) & 1) * 8 + (lane & 7)) * 144 +
                (lane >> 4) * 16;
#pragma unroll
            for (int f8 = 0; f8 < 8; f8 += 2) {
                uint32_t vb4[4];
                LDMX4T(vb4, vo + f8 * 16);
                MMA_F16(ctxa[f8],     pa, vb4);
                MMA_F16(ctxa[f8 + 1], pa, vb4 + 2);
            }
        }

        // stage p~ to PS, then coalesced copy to gmem
#pragma unroll
        for (int f = 0; f < 16; f++) {
            *reinterpret_cast<uint32_t*>(sm + PS + row0 * 272 + f * 16 + lc * 4) = ph0[f];
            *reinterpret_cast<uint32_t*>(sm + PS + (row0 + 8) * 272 + f * 16 + lc * 4) = ph1[f];
        }
        __syncthreads();
        {
            __half* dst = pscr + ((((size_t)bh * 16 + rb) * 16 + i) << 14);
            for (int c = tid; c < 2048; c += 256) {
                int r = c >> 4, ch = c & 15;
                *reinterpret_cast<uint4*>(dst + r * 128 + ch * 8) =
                    *reinterpret_cast<uint4*>(sm + PS + r * 272 + ch * 16);
            }
        }
        __syncthreads();
        if (i + 2 < 16) produce(i + 2);
    }

    // ---- one-time row-sum reduction over quad columns ----
    sum0 += __shfl_xor_sync(0xffffffffu, sum0, 1);
    sum0 += __shfl_xor_sync(0xffffffffu, sum0, 2);
    sum1 += __shfl_xor_sync(0xffffffffu, sum1, 1);
    sum1 += __shfl_xor_sync(0xffffffffu, sum1, 2);
    const float inv0 = 1.0f / sum0, inv1 = 1.0f / sum1;
    if (lc == 0) {
        float* ip = invg + ((size_t)bh * 16 + rb) * 128;
        ip[row0]     = inv0;
        ip[row0 + 8] = inv1;
    }

    // ---- ctx epilogue: scale by inv, stage via QS, write fp16 ----
#pragma unroll
    for (int f8 = 0; f8 < 8; f8++) {
        __half2 c01 = __floats2half2_rn(ctxa[f8][0] * inv0, ctxa[f8][1] * inv0);
        __half2 c23 = __floats2half2_rn(ctxa[f8][2] * inv1, ctxa[f8][3] * inv1);
        *reinterpret_cast<uint32_t*>(sm + QS + row0 * 144 + f8 * 16 + lc * 4) =
            *reinterpret_cast<uint32_t*>(&c01);
        *reinterpret_cast<uint32_t*>(sm + QS + (row0 + 8) * 144 + f8 * 16 + lc * 4) =
            *reinterpret_cast<uint32_t*>(&c23);
    }
    __syncthreads();
    {
        __half* dst = ctx + ((size_t)b * S_ + (size_t)rb * 128) * D_ + h * 64;
        for (int c = tid; c < 1024; c += 256) {
            int r = c >> 3, ch = c & 7;
            *reinterpret_cast<uint4*>(dst + (size_t)r * D_ + ch * 8) =
                *reinterpret_cast<uint4*>(sm + QS + r * 144 + ch * 16);
        }
    }
}

// ---------------- rescale p~ -> normalized fp32 attn (pure scale) ----------------
__global__ __launch_bounds__(256) void attn_rescale(
    const __half* __restrict__ pscr, const float* __restrict__ invg,
    float* __restrict__ attn)
{
    __shared__ float inv[128];
    const int blk = blockIdx.x;              // bh*16 + rb
    const int by  = blockIdx.y;              // row quarter
    const int bh = blk >> 4, rb = blk & 15;
    const int tid = threadIdx.x;
    if (tid < 128) inv[tid] = invg[(size_t)blk * 128 + tid];
    __syncthreads();
    const __half* src = pscr + ((size_t)blk << 18);
    float* dst = attn + ((size_t)bh * S_ + (size_t)rb * 128) * S_;
    const int ebase = by * 32 * 2048;
#pragma unroll 4
    for (int it = 0; it < 64; it++) {
        int e = ebase + (tid + it * 256) * 4;
        int r = e >> 11;
        int c = e & 2047;
        int t = c >> 7, tc = c & 127;
        uint2 pv = *reinterpret_cast<const uint2*>(src + ((size_t)t << 14) + r * 128 + tc);
        __half2 a  = *reinterpret_cast<__half2*>(&pv.x);
        __half2 b2 = *reinterpret_cast<__half2*>(&pv.y);
        float f = inv[r];
        float4 o;
        o.x = __half2float(a.x)  * f; o.y = __half2float(a.y)  * f;
        o.z = __half2float(b2.x) * f; o.w = __half2float(b2.y) * f;
        *reinterpret_cast<float4*>(dst + (size_t)r * S_ + c) = o;
    }
}

// ---------------- host ----------------
extern "C" void kernel_launch(void* const* d_in, const int* in_sizes, int n_in,
                              void* d_out, int out_size)
{
    const float* query = (const float*)d_in[0];
    const float* key   = (const float*)d_in[1];
    const float* value = (const float*)d_in[2];
    const float* Wq = (const float*)d_in[3];
    const float* bq = (const float*)d_in[4];
    const float* Wk = (const float*)d_in[5];
    const float* bk = (const float*)d_in[6];
    const float* Wv = (const float*)d_in[7];
    const float* bv = (const float*)d_in[8];
    const float* Wo = (const float*)d_in[9];
    const float* bo = (const float*)d_in[10];

    float* out  = (float*)d_out;
    float* attn = out + NELEM;

    __half *wt, *q16, *k16, *v16, *ctx, *ps;
    float* invb;
    cudaGetSymbolAddress((void**)&wt, g_wt);
    cudaGetSymbolAddress((void**)&q16, g_q16);
    cudaGetSymbolAddress((void**)&k16, g_k16);
    cudaGetSymbolAddress((void**)&v16, g_v16);
    cudaGetSymbolAddress((void**)&ctx, g_ctx);
    cudaGetSymbolAddress((void**)&ps, g_ps);
    cudaGetSymbolAddress((void**)&invb, g_inv);

    auto GPQKV = gemm_proj<true,  true>;    // QKV fused (A fp32 in-kernel cast) -> fp16
    auto GPOUT = gemm_proj<false, false>;   // out proj (A=ctx fp16) -> fp32
    const int SM_PROJ = 4 * 128 * 80;   // 40960
    cudaFuncSetAttribute(GPQKV, cudaFuncAttributeMaxDynamicSharedMemorySize, SM_PROJ);
    cudaFuncSetAttribute(GPOUT, cudaFuncAttributeMaxDynamicSharedMemorySize, SM_PROJ);
    const int SM_ATTN = 127488;
    cudaFuncSetAttribute(attn_fused, cudaFuncAttributeMaxDynamicSharedMemorySize, SM_ATTN);

    // 1) transpose weights -> fp16 W^T (one launch)
    wtrans_kernel<<<dim3(32, 32, 4), dim3(32, 8)>>>(Wq, Wk, Wv, Wo, wt);

    // 2) QKV projections in one launch, fp32->fp16 cast fused into A produce;
    //    Q folds 0.125*log2(e) for exp2-domain softmax
    gemm_proj<true, true><<<dim3(D_ / 128, (B_ * S_) / 128, 3), 256, SM_PROJ>>>(
        query, key, value, nullptr, wt, bq, bk, bv, nullptr, q16, k16, v16,
        0.125f * 1.4426950408889634f);

    // 3) fused attention: p~ scratch + row sums + fp16 ctx (V via ldmatrix.trans)
    attn_fused<<<dim3(16, B_ * H_), 256, SM_ATTN>>>(q16, k16, v16, ps, invb, ctx);

    // 4) rescale p~ -> normalized fp32 attn (pure per-row scale)
    attn_rescale<<<dim3(B_ * H_ * 16, 4), 256>>>(ps, invb, attn);

    // 5) out = ctx @ Wo + bo
    gemm_proj<false, false><<<dim3(D_ / 128, (B_ * S_) / 128, 1), 256, SM_PROJ>>>(
        nullptr, nullptr, nullptr, ctx, wt + 3 * D_ * D_, bo, nullptr, nullptr,
        out, nullptr, nullptr, nullptr, 1.0f);
}

// round 12
// speedup vs baseline: 1.0820x; 1.0820x over previous
#include <cuda_runtime.h>
#include <cuda_fp16.h>
#include <cstdint>

#define B_ 2
#define S_ 2048
#define D_ 1024
#define H_ 16
#define HD_ 64

#define NELEM ((size_t)B_ * S_ * D_)

// ---------------- scratch (allocation-free contract) ----------------
__device__ __half g_wt[4 * D_ * D_];        // W^T [n][k] fp16
__device__ __half g_q16[NELEM], g_k16[NELEM], g_v16[NELEM];
__device__ __half g_ctx[NELEM];
__device__ __half g_ps[(size_t)B_ * H_ * S_ * S_];   // p~ tiles (unnormalized exp2 scores)
__device__ float  g_inv[(size_t)B_ * H_ * 16 * 128]; // per (bh,rb,row): 1/sum

// ---------------- baseline-PTX helpers ----------------
__device__ __forceinline__ uint32_t smem_u32(const void* p) {
    uint32_t a;
    asm("{ .reg .u64 t; cvta.to.shared.u64 t, %1; cvt.u32.u64 %0, t; }" : "=r"(a) : "l"(p));
    return a;
}
__device__ __forceinline__ float ex2f(float x) {
    float y;
    asm("ex2.approx.ftz.f32 %0, %1;" : "=f"(y) : "f"(x));
    return y;
}
#define CP_ASYNC16(dst, src) \
    asm volatile("cp.async.cg.shared.global [%0], [%1], 16;" :: "r"(dst), "l"(src))
#define CP_COMMIT() asm volatile("cp.async.commit_group;" ::: "memory")
#define CP_WAIT1()  asm volatile("cp.async.wait_group 1;" ::: "memory")
#define CP_WAIT0()  asm volatile("cp.async.wait_group 0;" ::: "memory")

#define LDMX4(r, a) \
    asm volatile("ldmatrix.sync.aligned.m8n8.x4.shared.b16 {%0,%1,%2,%3}, [%4];" \
        : "=r"((r)[0]), "=r"((r)[1]), "=r"((r)[2]), "=r"((r)[3]) : "r"(a))
#define LDMX4T(r, a) \
    asm volatile("ldmatrix.sync.aligned.m8n8.x4.trans.shared.b16 {%0,%1,%2,%3}, [%4];" \
        : "=r"((r)[0]), "=r"((r)[1]), "=r"((r)[2]), "=r"((r)[3]) : "r"(a))

#define MMA_F16(d, a, b) \
    asm volatile("mma.sync.aligned.m16n8k16.row.col.f32.f16.f16.f32 " \
        "{%0,%1,%2,%3},{%4,%5,%6,%7},{%8,%9},{%0,%1,%2,%3};" \
        : "+f"((d)[0]), "+f"((d)[1]), "+f"((d)[2]), "+f"((d)[3]) \
        : "r"((a)[0]), "r"((a)[1]), "r"((a)[2]), "r"((a)[3]), "r"((b)[0]), "r"((b)[1]))

// ---------------- weight transpose -> fp16: W[k][n] -> Wt[n][k] ----------------
__global__ __launch_bounds__(256) void wtrans_kernel(
    const float* __restrict__ W0, const float* __restrict__ W1,
    const float* __restrict__ W2, const float* __restrict__ W3,
    __half* __restrict__ th)
{
    __shared__ float t[32][33];
    const int tx = threadIdx.x, ty = threadIdx.y;
    const int n0 = blockIdx.x * 32, k0 = blockIdx.y * 32;
    const int z = blockIdx.z;
    const float* W = z == 0 ? W0 : (z == 1 ? W1 : (z == 2 ? W2 : W3));
    __half* dst = th + (size_t)z * D_ * D_;
#pragma unroll
    for (int j = 0; j < 4; j++)
        t[ty + j * 8][tx] = W[(size_t)(k0 + ty + j * 8) * D_ + n0 + tx];
    __syncthreads();
#pragma unroll
    for (int j = 0; j < 4; j++)
        dst[(size_t)(n0 + ty + j * 8) * D_ + k0 + tx] = __float2half_rn(t[tx][ty + j * 8]);
}

// ---------------- projection GEMM (fp16 single-MMA) ----------------
// AFP32: A is fp32 in gmem, converted to fp16 in the produce stage (fused cast).
template <bool AFP32, bool OUT16>
__global__ __launch_bounds__(256, 2) void gemm_proj(
    const float* __restrict__ Af0, const float* __restrict__ Af1, const float* __restrict__ Af2,
    const __half* __restrict__ Ah,
    const __half* __restrict__ Wt,
    const float* __restrict__ b0, const float* __restrict__ b1, const float* __restrict__ b2,
    float* __restrict__ Cf,
    __half* __restrict__ C0, __half* __restrict__ C1, __half* __restrict__ C2,
    float scale0)
{
    extern __shared__ char smem[];
    constexpr uint32_t A_STAGE = 128 * 80;
    constexpr uint32_t B_BASE = 2 * A_STAGE;
    const uint32_t sbase = smem_u32(smem);

    const int tid = threadIdx.x;
    const int wid = tid >> 5, lane = tid & 31;
    const int wm0 = (wid >> 2) * 64;
    const int wn0 = (wid & 3) * 32;
    const int row0 = blockIdx.y * 128, col0 = blockIdx.x * 128;

    const int z = blockIdx.z;
    const float* Af = z == 0 ? Af0 : (z == 1 ? Af1 : Af2);
    const float* bias = z == 0 ? b0 : (z == 1 ? b1 : b2);
    __half* C16 = z == 0 ? C0 : (z == 1 ? C1 : C2);
    const float scale = z == 0 ? scale0 : 1.0f;
    const __half* W = Wt + (size_t)z * D_ * D_;

    float acc[4][4][4];
#pragma unroll
    for (int im = 0; im < 4; im++)
#pragma unroll
        for (int in_ = 0; in_ < 4; in_++)
#pragma unroll
            for (int j = 0; j < 4; j++) acc[im][in_][j] = 0.0f;

    auto produce = [&](int i) {
        const int st = i & 1;
        const int k0 = i << 5;
        if (AFP32) {
#pragma unroll
            for (int c = tid; c < 512; c += 256) {
                int r = c >> 2, kc = c & 3;
                const float* s = Af + (long long)(row0 + r) * D_ + k0 + kc * 8;
                float4 u0 = *reinterpret_cast<const float4*>(s);
                float4 u1 = *reinterpret_cast<const float4*>(s + 4);
                alignas(16) __half hh[8];
                hh[0] = __float2half_rn(u0.x); hh[1] = __float2half_rn(u0.y);
                hh[2] = __float2half_rn(u0.z); hh[3] = __float2half_rn(u0.w);
                hh[4] = __float2half_rn(u1.x); hh[5] = __float2half_rn(u1.y);
                hh[6] = __float2half_rn(u1.z); hh[7] = __float2half_rn(u1.w);
                *reinterpret_cast<uint4*>(smem + st * A_STAGE + (uint32_t)(r * 80 + kc * 16)) =
                    *reinterpret_cast<uint4*>(hh);
            }
        } else {
#pragma unroll
            for (int c = tid; c < 512; c += 256) {
                int r = c >> 2, kc = c & 3;
                CP_ASYNC16(sbase + st * A_STAGE + (uint32_t)(r * 80 + kc * 16),
                           Ah + (long long)(row0 + r) * D_ + k0 + kc * 8);
            }
        }
#pragma unroll
        for (int c = tid; c < 512; c += 256) {
            int r = c >> 2, kc = c & 3;
            CP_ASYNC16(sbase + B_BASE + st * A_STAGE + (uint32_t)(r * 80 + kc * 16),
                       W + (long long)(col0 + r) * D_ + k0 + kc * 8);
        }
        CP_COMMIT();
    };

    auto compute = [&](int st) {
        const uint32_t bA = sbase + st * A_STAGE;
        const uint32_t bB = sbase + B_BASE + st * A_STAGE;
#pragma unroll
        for (int k2 = 0; k2 < 2; k2++) {
            uint32_t ah[4][4];
            const uint32_t ao = (uint32_t)((wm0 + (lane & 15)) * 80 +
                                           (k2 * 16 + (lane >> 4) * 8) * 2);
#pragma unroll
            for (int im = 0; im < 4; im++)
                LDMX4(ah[im], bA + ao + im * (16 * 80));
            const uint32_t bo = (uint32_t)((wn0 + (lane >> 4) * 8 + (lane & 7)) * 80 +
                                           k2 * 32 + ((lane >> 3) & 1) * 16);
#pragma unroll
            for (int in_ = 0; in_ < 4; in_ += 2) {
                uint32_t bh4[4];
                LDMX4(bh4, bo + bB + in_ * (8 * 80));
#pragma unroll
                for (int im = 0; im < 4; im++) {
                    MMA_F16(acc[im][in_], ah[im], bh4);
                    MMA_F16(acc[im][in_ + 1], ah[im], bh4 + 2);
                }
            }
        }
    };

    const int NS = D_ >> 5;
    produce(0);
    produce(1);
    for (int i = 0; i < NS; i++) {
        if (i + 1 < NS) { CP_WAIT1(); } else { CP_WAIT0(); }
        __syncthreads();
        compute(i & 1);
        __syncthreads();
        if (i + 2 < NS) produce(i + 2);
    }

    const int qrow = lane >> 2;
    const int qcol = (lane & 3) * 2;
#pragma unroll
    for (int im = 0; im < 4; im++) {
#pragma unroll
        for (int half_ = 0; half_ < 2; half_++) {
            const int m = row0 + wm0 + im * 16 + qrow + half_ * 8;
#pragma unroll
            for (int in_ = 0; in_ < 4; in_++) {
                const int n = col0 + wn0 + in_ * 8 + qcol;
                float v0 = (acc[im][in_][half_ * 2 + 0] + bias[n])     * scale;
                float v1 = (acc[im][in_][half_ * 2 + 1] + bias[n + 1]) * scale;
                const long long o = (long long)m * D_ + n;
                if (OUT16) {
                    __half2 hp = __floats2half2_rn(v0, v1);
                    *reinterpret_cast<uint32_t*>(C16 + o) = *reinterpret_cast<uint32_t*>(&hp);
                } else {
                    *reinterpret_cast<float2*>(Cf + o) = make_float2(v0, v1);
                }
            }
        }
    }
}

// ---------------- fused attention: scores + exp2 (no max-shift) + PV ----------------
// grid (rb=S/128, bh-chunk). bh = bh0 + blockIdx.y.
__global__ __launch_bounds__(256, 1) void attn_fused(
    const __half* __restrict__ q16, const __half* __restrict__ k16,
    const __half* __restrict__ v16,
    __half* __restrict__ pscr, float* __restrict__ invg,
    __half* __restrict__ ctx, int bh0)
{
    extern __shared__ char sm[];
    const uint32_t sb = smem_u32(sm);
    constexpr uint32_t QS = 0;
    constexpr uint32_t KS = 18432;
    constexpr uint32_t VS = 18432 + 36864;           // 55296
    constexpr uint32_t PS = 55296 + 36864;           // 92160
    const int tid = threadIdx.x, w = tid >> 5, lane = tid & 31;
    const int rb = blockIdx.x, bh = bh0 + blockIdx.y, b = bh >> 4, h = bh & 15;
    const int lr = lane >> 2, lc = lane & 3;
    const int row0 = w * 16 + lr;

    // q tile (group 0)
    {
        const __half* src = q16 + ((size_t)b * S_ + (size_t)rb * 128) * D_ + h * 64;
        for (int c = tid; c < 1024; c += 256) {
            int r = c >> 3, ch = c & 7;
            CP_ASYNC16(sb + QS + r * 144 + ch * 16, src + (size_t)r * D_ + ch * 8);
        }
        CP_COMMIT();
    }
    auto produce = [&](int i) {
        int st = i & 1;
        const __half* ks = k16 + ((size_t)b * S_ + (size_t)i * 128) * D_ + h * 64;
        const __half* vs = v16 + ((size_t)b * S_ + (size_t)i * 128) * D_ + h * 64;
        for (int c = tid; c < 1024; c += 256) {
            int r = c >> 3, ch = c & 7;
            CP_ASYNC16(sb + KS + st * 18432 + r * 144 + ch * 16, ks + (size_t)r * D_ + ch * 8);
            CP_ASYNC16(sb + VS + st * 18432 + r * 144 + ch * 16, vs + (size_t)r * D_ + ch * 8);
        }
        CP_COMMIT();
    };
    produce(0);
    produce(1);

    uint32_t qa[4][4];
    float ctxa[8][4];
#pragma unroll
    for (int f8 = 0; f8 < 8; f8++)
#pragma unroll
        for (int j = 0; j < 4; j++) ctxa[f8][j] = 0.0f;
    float sum0 = 0.0f, sum1 = 0.0f;

    for (int i = 0; i < 16; i++) {
        if (i + 1 < 16) { CP_WAIT1(); } else { CP_WAIT0(); }
        __syncthreads();
        if (i == 0) {
#pragma unroll
            for (int kc = 0; kc < 4; kc++)
                LDMX4(qa[kc], sb + QS + (w * 16 + (lane & 15)) * 144 +
                              (kc * 16 + (lane >> 4) * 8) * 2);
        }
        const uint32_t kbuf = sb + KS + (i & 1) * 18432;
        const uint32_t vbuf = sb + VS + (i & 1) * 18432;

        // s = q @ k^T (exp2 domain)
        float sa[16][4];
#pragma unroll
        for (int f = 0; f < 16; f++) {
            sa[f][0] = sa[f][1] = sa[f][2] = sa[f][3] = 0.0f;
        }
#pragma unroll
        for (int kc = 0; kc < 4; kc++) {
            const uint32_t ko = kbuf + ((lane >> 4) * 8 + (lane & 7)) * 144 +
                                kc * 32 + ((lane >> 3) & 1) * 16;
#pragma unroll
            for (int f = 0; f < 16; f += 2) {
                uint32_t kb4[4];
                LDMX4(kb4, ko + f * (8 * 144));
                MMA_F16(sa[f],     qa[kc], kb4);
                MMA_F16(sa[f + 1], qa[kc], kb4 + 2);
            }
        }

        // p~ = exp2(s), per-thread partial sums, fp16 pack (no max shift)
        uint32_t ph0[16], ph1[16];
#pragma unroll
        for (int f = 0; f < 16; f++) {
            float p0 = ex2f(sa[f][0]), p1 = ex2f(sa[f][1]);
            float p2 = ex2f(sa[f][2]), p3 = ex2f(sa[f][3]);
            sum0 += p0 + p1; sum1 += p2 + p3;
            __half2 h01 = __floats2half2_rn(p0, p1);
            __half2 h23 = __floats2half2_rn(p2, p3);
            ph0[f] = *reinterpret_cast<uint32_t*>(&h01);
            ph1[f] = *reinterpret_cast<uint32_t*>(&h23);
        }

        // ctx += p~ @ v   (V in [s, hd] layout; ldmatrix.trans B-frags)
#pragma unroll
        for (int ks2 = 0; ks2 < 8; ks2++) {
            uint32_t pa[4] = { ph0[2 * ks2], ph1[2 * ks2],
                               ph0[2 * ks2 + 1], ph1[2 * ks2 + 1] };
            const uint32_t vo = vbuf +
                (ks2 * 16 + ((lane >> 3) & 1) * 8 + (lane & 7)) * 144 +
                (lane >> 4) * 16;
#pragma unroll
            for (int f8 = 0; f8 < 8; f8 += 2) {
                uint32_t vb4[4];
                LDMX4T(vb4, vo + f8 * 16);
                MMA_F16(ctxa[f8],     pa, vb4);
                MMA_F16(ctxa[f8 + 1], pa, vb4 + 2);
            }
        }

        // stage p~ to PS, then coalesced copy to gmem
#pragma unroll
        for (int f = 0; f < 16; f++) {
            *reinterpret_cast<uint32_t*>(sm + PS + row0 * 272 + f * 16 + lc * 4) = ph0[f];
            *reinterpret_cast<uint32_t*>(sm + PS + (row0 + 8) * 272 + f * 16 + lc * 4) = ph1[f];
        }
        __syncthreads();
        {
            __half* dst = pscr + ((((size_t)bh * 16 + rb) * 16 + i) << 14);
            for (int c = tid; c < 2048; c += 256) {
                int r = c >> 4, ch = c & 15;
                *reinterpret_cast<uint4*>(dst + r * 128 + ch * 8) =
                    *reinterpret_cast<uint4*>(sm + PS + r * 272 + ch * 16);
            }
        }
        __syncthreads();
        if (i + 2 < 16) produce(i + 2);
    }

    // ---- one-time row-sum reduction over quad columns ----
    sum0 += __shfl_xor_sync(0xffffffffu, sum0, 1);
    sum0 += __shfl_xor_sync(0xffffffffu, sum0, 2);
    sum1 += __shfl_xor_sync(0xffffffffu, sum1, 1);
    sum1 += __shfl_xor_sync(0xffffffffu, sum1, 2);
    const float inv0 = 1.0f / sum0, inv1 = 1.0f / sum1;
    if (lc == 0) {
        float* ip = invg + ((size_t)bh * 16 + rb) * 128;
        ip[row0]     = inv0;
        ip[row0 + 8] = inv1;
    }

    // ---- ctx epilogue: scale by inv, stage via QS, write fp16 ----
#pragma unroll
    for (int f8 = 0; f8 < 8; f8++) {
        __half2 c01 = __floats2half2_rn(ctxa[f8][0] * inv0, ctxa[f8][1] * inv0);
        __half2 c23 = __floats2half2_rn(ctxa[f8][2] * inv1, ctxa[f8][3] * inv1);
        *reinterpret_cast<uint32_t*>(sm + QS + row0 * 144 + f8 * 16 + lc * 4) =
            *reinterpret_cast<uint32_t*>(&c01);
        *reinterpret_cast<uint32_t*>(sm + QS + (row0 + 8) * 144 + f8 * 16 + lc * 4) =
            *reinterpret_cast<uint32_t*>(&c23);
    }
    __syncthreads();
    {
        __half* dst = ctx + ((size_t)b * S_ + (size_t)rb * 128) * D_ + h * 64;
        for (int c = tid; c < 1024; c += 256) {
            int r = c >> 3, ch = c & 7;
            *reinterpret_cast<uint4*>(dst + (size_t)r * D_ + ch * 8) =
                *reinterpret_cast<uint4*>(sm + QS + r * 144 + ch * 16);
        }
    }
}

// ---------------- rescale p~ -> normalized fp32 attn (pure scale) ----------------
__global__ __launch_bounds__(256) void attn_rescale(
    const __half* __restrict__ pscr, const float* __restrict__ invg,
    float* __restrict__ attn, int blk0)
{
    __shared__ float inv[128];
    const int blk = blk0 + blockIdx.x;       // bh*16 + rb
    const int by  = blockIdx.y;              // row quarter
    const int bh = blk >> 4, rb = blk & 15;
    const int tid = threadIdx.x;
    if (tid < 128) inv[tid] = invg[(size_t)blk * 128 + tid];
    __syncthreads();
    const __half* src = pscr + ((size_t)blk << 18);
    float* dst = attn + ((size_t)bh * S_ + (size_t)rb * 128) * S_;
    const int ebase = by * 32 * 2048;
#pragma unroll 4
    for (int it = 0; it < 64; it++) {
        int e = ebase + (tid + it * 256) * 4;
        int r = e >> 11;
        int c = e & 2047;
        int t = c >> 7, tc = c & 127;
        uint2 pv = *reinterpret_cast<const uint2*>(src + ((size_t)t << 14) + r * 128 + tc);
        __half2 a  = *reinterpret_cast<__half2*>(&pv.x);
        __half2 b2 = *reinterpret_cast<__half2*>(&pv.y);
        float f = inv[r];
        float4 o;
        o.x = __half2float(a.x)  * f; o.y = __half2float(a.y)  * f;
        o.z = __half2float(b2.x) * f; o.w = __half2float(b2.y) * f;
        *reinterpret_cast<float4*>(dst + (size_t)r * S_ + c) = o;
    }
}

// ---------------- host ----------------
extern "C" void kernel_launch(void* const* d_in, const int* in_sizes, int n_in,
                              void* d_out, int out_size)
{
    const float* query = (const float*)d_in[0];
    const float* key   = (const float*)d_in[1];
    const float* value = (const float*)d_in[2];
    const float* Wq = (const float*)d_in[3];
    const float* bq = (const float*)d_in[4];
    const float* Wk = (const float*)d_in[5];
    const float* bk = (const float*)d_in[6];
    const float* Wv = (const float*)d_in[7];
    const float* bv = (const float*)d_in[8];
    const float* Wo = (const float*)d_in[9];
    const float* bo = (const float*)d_in[10];

    float* out  = (float*)d_out;
    float* attn = out + NELEM;

    __half *wt, *q16, *k16, *v16, *ctx, *ps;
    float* invb;
    cudaGetSymbolAddress((void**)&wt, g_wt);
    cudaGetSymbolAddress((void**)&q16, g_q16);
    cudaGetSymbolAddress((void**)&k16, g_k16);
    cudaGetSymbolAddress((void**)&v16, g_v16);
    cudaGetSymbolAddress((void**)&ctx, g_ctx);
    cudaGetSymbolAddress((void**)&ps, g_ps);
    cudaGetSymbolAddress((void**)&invb, g_inv);

    // One-time stream/event creation (first call is the uncaptured correctness
    // run; capture calls reuse the handles — the documented fork/join idiom).
    static cudaStream_t s2 = []() {
        cudaStream_t s; cudaStreamCreateWithFlags(&s, cudaStreamNonBlocking); return s;
    }();
    static cudaEvent_t evF0 = []() {
        cudaEvent_t e; cudaEventCreateWithFlags(&e, cudaEventDisableTiming); return e;
    }();
    static cudaEvent_t evF1 = []() {
        cudaEvent_t e; cudaEventCreateWithFlags(&e, cudaEventDisableTiming); return e;
    }();
    static cudaEvent_t evJoin = []() {
        cudaEvent_t e; cudaEventCreateWithFlags(&e, cudaEventDisableTiming); return e;
    }();

    auto GPQKV = gemm_proj<true,  true>;
    auto GPOUT = gemm_proj<false, false>;
    const int SM_PROJ = 4 * 128 * 80;   // 40960
    cudaFuncSetAttribute(GPQKV, cudaFuncAttributeMaxDynamicSharedMemorySize, SM_PROJ);
    cudaFuncSetAttribute(GPOUT, cudaFuncAttributeMaxDynamicSharedMemorySize, SM_PROJ);
    const int SM_ATTN = 127488;
    cudaFuncSetAttribute(attn_fused, cudaFuncAttributeMaxDynamicSharedMemorySize, SM_ATTN);

    // 1) transpose weights -> fp16 W^T
    wtrans_kernel<<<dim3(32, 32, 4), dim3(32, 8)>>>(Wq, Wk, Wv, Wo, wt);

    // 2) QKV projections (fused fp32->fp16 cast); Q folds 0.125*log2(e)
    gemm_proj<true, true><<<dim3(D_ / 128, (B_ * S_) / 128, 3), 256, SM_PROJ>>>(
        query, key, value, nullptr, wt, bq, bk, bv, nullptr, q16, k16, v16,
        0.125f * 1.4426950408889634f);

    // 3a) fused attention, bh half 0
    attn_fused<<<dim3(16, 16), 256, SM_ATTN>>>(q16, k16, v16, ps, invb, ctx, 0);
    cudaEventRecord(evF0, 0);

    // 3b) fused attention, bh half 1 (main stream, overlaps rescale half 0)
    attn_fused<<<dim3(16, 16), 256, SM_ATTN>>>(q16, k16, v16, ps, invb, ctx, 16);
    cudaEventRecord(evF1, 0);

    // 4a) rescale half 0 on s2, concurrent with fused half 1
    cudaStreamWaitEvent(s2, evF0, 0);
    attn_rescale<<<dim3(256, 4), 256, 0, s2>>>(ps, invb, attn, 0);

    // 4b) rescale half 1 on s2, concurrent with out projection
    cudaStreamWaitEvent(s2, evF1, 0);
    attn_rescale<<<dim3(256, 4), 256, 0, s2>>>(ps, invb, attn, 256);
    cudaEventRecord(evJoin, s2);

    // 5) out = ctx @ Wo + bo (needs both ctx halves; main stream)
    gemm_proj<false, false><<<dim3(D_ / 128, (B_ * S_) / 128, 1), 256, SM_PROJ>>>(
        nullptr, nullptr, nullptr, ctx, wt + 3 * D_ * D_, bo, nullptr, nullptr,
        out, nullptr, nullptr, nullptr, 1.0f);

    // join: main stream completion implies rescale done
    cudaStreamWaitEvent(0, evJoin, 0);
}

// round 13
// speedup vs baseline: 1.1216x; 1.0365x over previous
#include <cuda_runtime.h>
#include <cuda_fp16.h>
#include <cstdint>

#define B_ 2
#define S_ 2048
#define D_ 1024
#define H_ 16
#define HD_ 64

#define NELEM ((size_t)B_ * S_ * D_)

// ---------------- scratch (allocation-free contract) ----------------
__device__ __half g_wt[4 * D_ * D_];        // W^T [n][k] fp16
__device__ __half g_q16[NELEM], g_k16[NELEM], g_v16[NELEM];
__device__ __half g_ctx[NELEM];
__device__ __half g_ps[(size_t)B_ * H_ * S_ * S_];   // p~ tiles (64x128 each)
__device__ float  g_inv[(size_t)B_ * H_ * 32 * 64];  // per (bh,rb64,row): 1/sum

// ---------------- baseline-PTX helpers ----------------
__device__ __forceinline__ uint32_t smem_u32(const void* p) {
    uint32_t a;
    asm("{ .reg .u64 t; cvta.to.shared.u64 t, %1; cvt.u32.u64 %0, t; }" : "=r"(a) : "l"(p));
    return a;
}
__device__ __forceinline__ float ex2f(float x) {
    float y;
    asm("ex2.approx.ftz.f32 %0, %1;" : "=f"(y) : "f"(x));
    return y;
}
#define CP_ASYNC16(dst, src) \
    asm volatile("cp.async.cg.shared.global [%0], [%1], 16;" :: "r"(dst), "l"(src))
#define CP_COMMIT() asm volatile("cp.async.commit_group;" ::: "memory")
#define CP_WAIT1()  asm volatile("cp.async.wait_group 1;" ::: "memory")
#define CP_WAIT0()  asm volatile("cp.async.wait_group 0;" ::: "memory")

#define LDMX4(r, a) \
    asm volatile("ldmatrix.sync.aligned.m8n8.x4.shared.b16 {%0,%1,%2,%3}, [%4];" \
        : "=r"((r)[0]), "=r"((r)[1]), "=r"((r)[2]), "=r"((r)[3]) : "r"(a))
#define LDMX4T(r, a) \
    asm volatile("ldmatrix.sync.aligned.m8n8.x4.trans.shared.b16 {%0,%1,%2,%3}, [%4];" \
        : "=r"((r)[0]), "=r"((r)[1]), "=r"((r)[2]), "=r"((r)[3]) : "r"(a))

#define MMA_F16(d, a, b) \
    asm volatile("mma.sync.aligned.m16n8k16.row.col.f32.f16.f16.f32 " \
        "{%0,%1,%2,%3},{%4,%5,%6,%7},{%8,%9},{%0,%1,%2,%3};" \
        : "+f"((d)[0]), "+f"((d)[1]), "+f"((d)[2]), "+f"((d)[3]) \
        : "r"((a)[0]), "r"((a)[1]), "r"((a)[2]), "r"((a)[3]), "r"((b)[0]), "r"((b)[1]))

// ---------------- weight transpose -> fp16: W[k][n] -> Wt[n][k] ----------------
__global__ __launch_bounds__(256) void wtrans_kernel(
    const float* __restrict__ W0, const float* __restrict__ W1,
    const float* __restrict__ W2, const float* __restrict__ W3,
    __half* __restrict__ th)
{
    __shared__ float t[32][33];
    const int tx = threadIdx.x, ty = threadIdx.y;
    const int n0 = blockIdx.x * 32, k0 = blockIdx.y * 32;
    const int z = blockIdx.z;
    const float* W = z == 0 ? W0 : (z == 1 ? W1 : (z == 2 ? W2 : W3));
    __half* dst = th + (size_t)z * D_ * D_;
#pragma unroll
    for (int j = 0; j < 4; j++)
        t[ty + j * 8][tx] = W[(size_t)(k0 + ty + j * 8) * D_ + n0 + tx];
    __syncthreads();
#pragma unroll
    for (int j = 0; j < 4; j++)
        dst[(size_t)(n0 + ty + j * 8) * D_ + k0 + tx] = __float2half_rn(t[tx][ty + j * 8]);
}

// ---------------- projection GEMM (fp16 single-MMA) ----------------
template <bool AFP32, bool OUT16>
__global__ __launch_bounds__(256, 2) void gemm_proj(
    const float* __restrict__ Af0, const float* __restrict__ Af1, const float* __restrict__ Af2,
    const __half* __restrict__ Ah,
    const __half* __restrict__ Wt,
    const float* __restrict__ b0, const float* __restrict__ b1, const float* __restrict__ b2,
    float* __restrict__ Cf,
    __half* __restrict__ C0, __half* __restrict__ C1, __half* __restrict__ C2,
    float scale0)
{
    extern __shared__ char smem[];
    constexpr uint32_t A_STAGE = 128 * 80;
    constexpr uint32_t B_BASE = 2 * A_STAGE;
    const uint32_t sbase = smem_u32(smem);

    const int tid = threadIdx.x;
    const int wid = tid >> 5, lane = tid & 31;
    const int wm0 = (wid >> 2) * 64;
    const int wn0 = (wid & 3) * 32;
    const int row0 = blockIdx.y * 128, col0 = blockIdx.x * 128;

    const int z = blockIdx.z;
    const float* Af = z == 0 ? Af0 : (z == 1 ? Af1 : Af2);
    const float* bias = z == 0 ? b0 : (z == 1 ? b1 : b2);
    __half* C16 = z == 0 ? C0 : (z == 1 ? C1 : C2);
    const float scale = z == 0 ? scale0 : 1.0f;
    const __half* W = Wt + (size_t)z * D_ * D_;

    float acc[4][4][4];
#pragma unroll
    for (int im = 0; im < 4; im++)
#pragma unroll
        for (int in_ = 0; in_ < 4; in_++)
#pragma unroll
            for (int j = 0; j < 4; j++) acc[im][in_][j] = 0.0f;

    auto produce = [&](int i) {
        const int st = i & 1;
        const int k0 = i << 5;
        if (AFP32) {
#pragma unroll
            for (int c = tid; c < 512; c += 256) {
                int r = c >> 2, kc = c & 3;
                const float* s = Af + (long long)(row0 + r) * D_ + k0 + kc * 8;
                float4 u0 = *reinterpret_cast<const float4*>(s);
                float4 u1 = *reinterpret_cast<const float4*>(s + 4);
                alignas(16) __half hh[8];
                hh[0] = __float2half_rn(u0.x); hh[1] = __float2half_rn(u0.y);
                hh[2] = __float2half_rn(u0.z); hh[3] = __float2half_rn(u0.w);
                hh[4] = __float2half_rn(u1.x); hh[5] = __float2half_rn(u1.y);
                hh[6] = __float2half_rn(u1.z); hh[7] = __float2half_rn(u1.w);
                *reinterpret_cast<uint4*>(smem + st * A_STAGE + (uint32_t)(r * 80 + kc * 16)) =
                    *reinterpret_cast<uint4*>(hh);
            }
        } else {
#pragma unroll
            for (int c = tid; c < 512; c += 256) {
                int r = c >> 2, kc = c & 3;
                CP_ASYNC16(sbase + st * A_STAGE + (uint32_t)(r * 80 + kc * 16),
                           Ah + (long long)(row0 + r) * D_ + k0 + kc * 8);
            }
        }
#pragma unroll
        for (int c = tid; c < 512; c += 256) {
            int r = c >> 2, kc = c & 3;
            CP_ASYNC16(sbase + B_BASE + st * A_STAGE + (uint32_t)(r * 80 + kc * 16),
                       W + (long long)(col0 + r) * D_ + k0 + kc * 8);
        }
        CP_COMMIT();
    };

    auto compute = [&](int st) {
        const uint32_t bA = sbase + st * A_STAGE;
        const uint32_t bB = sbase + B_BASE + st * A_STAGE;
#pragma unroll
        for (int k2 = 0; k2 < 2; k2++) {
            uint32_t ah[4][4];
            const uint32_t ao = (uint32_t)((wm0 + (lane & 15)) * 80 +
                                           (k2 * 16 + (lane >> 4) * 8) * 2);
#pragma unroll
            for (int im = 0; im < 4; im++)
                LDMX4(ah[im], bA + ao + im * (16 * 80));
            const uint32_t bo = (uint32_t)((wn0 + (lane >> 4) * 8 + (lane & 7)) * 80 +
                                           k2 * 32 + ((lane >> 3) & 1) * 16);
#pragma unroll
            for (int in_ = 0; in_ < 4; in_ += 2) {
                uint32_t bh4[4];
                LDMX4(bh4, bo + bB + in_ * (8 * 80));
#pragma unroll
                for (int im = 0; im < 4; im++) {
                    MMA_F16(acc[im][in_], ah[im], bh4);
                    MMA_F16(acc[im][in_ + 1], ah[im], bh4 + 2);
                }
            }
        }
    };

    const int NS = D_ >> 5;
    produce(0);
    produce(1);
    for (int i = 0; i < NS; i++) {
        if (i + 1 < NS) { CP_WAIT1(); } else { CP_WAIT0(); }
        __syncthreads();
        compute(i & 1);
        __syncthreads();
        if (i + 2 < NS) produce(i + 2);
    }

    const int qrow = lane >> 2;
    const int qcol = (lane & 3) * 2;
#pragma unroll
    for (int im = 0; im < 4; im++) {
#pragma unroll
        for (int half_ = 0; half_ < 2; half_++) {
            const int m = row0 + wm0 + im * 16 + qrow + half_ * 8;
#pragma unroll
            for (int in_ = 0; in_ < 4; in_++) {
                const int n = col0 + wn0 + in_ * 8 + qcol;
                float v0 = (acc[im][in_][half_ * 2 + 0] + bias[n])     * scale;
                float v1 = (acc[im][in_][half_ * 2 + 1] + bias[n + 1]) * scale;
                const long long o = (long long)m * D_ + n;
                if (OUT16) {
                    __half2 hp = __floats2half2_rn(v0, v1);
                    *reinterpret_cast<uint32_t*>(C16 + o) = *reinterpret_cast<uint32_t*>(&hp);
                } else {
                    *reinterpret_cast<float2*>(Cf + o) = make_float2(v0, v1);
                }
            }
        }
    }
}

// ---------------- fused attention: BM=64, 4 warps, 2 CTAs/SM ----------------
// grid (rb=S/64, bh-chunk). bh = bh0 + blockIdx.y. Warp w owns q-rows [w*16, w*16+16).
// q16 pre-scaled by 0.125*log2(e); exp2-domain, no max shift.
// smem: KS 2x128x144 | VS 2x128x144 | PS 64x272 (QS aliased into PS)
__global__ __launch_bounds__(128, 2) void attn_fused(
    const __half* __restrict__ q16, const __half* __restrict__ k16,
    const __half* __restrict__ v16,
    __half* __restrict__ pscr, float* __restrict__ invg,
    __half* __restrict__ ctx, int bh0)
{
    extern __shared__ char sm[];
    const uint32_t sb = smem_u32(sm);
    constexpr uint32_t KS = 0;                 // 2 * 18432
    constexpr uint32_t VS = 36864;             // 2 * 18432
    constexpr uint32_t PS = 73728;             // 64*272 = 17408 (end 91136)
    constexpr uint32_t QS = PS;                // q tile 64*144 = 9216, consumed at i=0
    const int tid = threadIdx.x, w = tid >> 5, lane = tid & 31;
    const int rb = blockIdx.x, bh = bh0 + blockIdx.y, b = bh >> 4, h = bh & 15;
    const int lr = lane >> 2, lc = lane & 3;
    const int row0 = w * 16 + lr;              // 0..63

    // q tile (group 0): 64 rows
    {
        const __half* src = q16 + ((size_t)b * S_ + (size_t)rb * 64) * D_ + h * 64;
        for (int c = tid; c < 512; c += 128) {
            int r = c >> 3, ch = c & 7;
            CP_ASYNC16(sb + QS + r * 144 + ch * 16, src + (size_t)r * D_ + ch * 8);
        }
        CP_COMMIT();
    }
    auto produce = [&](int i) {
        int st = i & 1;
        const __half* ks = k16 + ((size_t)b * S_ + (size_t)i * 128) * D_ + h * 64;
        const __half* vs = v16 + ((size_t)b * S_ + (size_t)i * 128) * D_ + h * 64;
        for (int c = tid; c < 1024; c += 128) {
            int r = c >> 3, ch = c & 7;
            CP_ASYNC16(sb + KS + st * 18432 + r * 144 + ch * 16, ks + (size_t)r * D_ + ch * 8);
            CP_ASYNC16(sb + VS + st * 18432 + r * 144 + ch * 16, vs + (size_t)r * D_ + ch * 8);
        }
        CP_COMMIT();
    };
    produce(0);
    produce(1);

    uint32_t qa[4][4];
    float ctxa[8][4];
#pragma unroll
    for (int f8 = 0; f8 < 8; f8++)
#pragma unroll
        for (int j = 0; j < 4; j++) ctxa[f8][j] = 0.0f;
    float sum0 = 0.0f, sum1 = 0.0f;

    for (int i = 0; i < 16; i++) {
        if (i + 1 < 16) { CP_WAIT1(); } else { CP_WAIT0(); }
        __syncthreads();
        if (i == 0) {
#pragma unroll
            for (int kc = 0; kc < 4; kc++)
                LDMX4(qa[kc], sb + QS + (w * 16 + (lane & 15)) * 144 +
                              (kc * 16 + (lane >> 4) * 8) * 2);
        }
        const uint32_t kbuf = sb + KS + (i & 1) * 18432;
        const uint32_t vbuf = sb + VS + (i & 1) * 18432;

        // s = q @ k^T (exp2 domain)
        float sa[16][4];
#pragma unroll
        for (int f = 0; f < 16; f++) {
            sa[f][0] = sa[f][1] = sa[f][2] = sa[f][3] = 0.0f;
        }
#pragma unroll
        for (int kc = 0; kc < 4; kc++) {
            const uint32_t ko = kbuf + ((lane >> 4) * 8 + (lane & 7)) * 144 +
                                kc * 32 + ((lane >> 3) & 1) * 16;
#pragma unroll
            for (int f = 0; f < 16; f += 2) {
                uint32_t kb4[4];
                LDMX4(kb4, ko + f * (8 * 144));
                MMA_F16(sa[f],     qa[kc], kb4);
                MMA_F16(sa[f + 1], qa[kc], kb4 + 2);
            }
        }

        // p~ = exp2(s), per-thread partial sums, fp16 pack (no max shift)
        uint32_t ph0[16], ph1[16];
#pragma unroll
        for (int f = 0; f < 16; f++) {
            float p0 = ex2f(sa[f][0]), p1 = ex2f(sa[f][1]);
            float p2 = ex2f(sa[f][2]), p3 = ex2f(sa[f][3]);
            sum0 += p0 + p1; sum1 += p2 + p3;
            __half2 h01 = __floats2half2_rn(p0, p1);
            __half2 h23 = __floats2half2_rn(p2, p3);
            ph0[f] = *reinterpret_cast<uint32_t*>(&h01);
            ph1[f] = *reinterpret_cast<uint32_t*>(&h23);
        }

        // ctx += p~ @ v   (V in [s, hd] layout; ldmatrix.trans B-frags)
#pragma unroll
        for (int ks2 = 0; ks2 < 8; ks2++) {
            uint32_t pa[4] = { ph0[2 * ks2], ph1[2 * ks2],
                               ph0[2 * ks2 + 1], ph1[2 * ks2 + 1] };
            const uint32_t vo = vbuf +
                (ks2 * 16 + ((lane >> 3) & 1) * 8 + (lane & 7)) * 144 +
                (lane >> 4) * 16;
#pragma unroll
            for (int f8 = 0; f8 < 8; f8 += 2) {
                uint32_t vb4[4];
                LDMX4T(vb4, vo + f8 * 16);
                MMA_F16(ctxa[f8],     pa, vb4);
                MMA_F16(ctxa[f8 + 1], pa, vb4 + 2);
            }
        }

        // stage p~ to PS, then coalesced copy to gmem (64x128 tile)
#pragma unroll
        for (int f = 0; f < 16; f++) {
            *reinterpret_cast<uint32_t*>(sm + PS + row0 * 272 + f * 16 + lc * 4) = ph0[f];
            *reinterpret_cast<uint32_t*>(sm + PS + (row0 + 8) * 272 + f * 16 + lc * 4) = ph1[f];
        }
        __syncthreads();
        {
            __half* dst = pscr + ((((size_t)bh * 32 + rb) * 16 + i) << 13);
            for (int c = tid; c < 1024; c += 128) {
                int r = c >> 4, ch = c & 15;
                *reinterpret_cast<uint4*>(dst + r * 128 + ch * 8) =
                    *reinterpret_cast<uint4*>(sm + PS + r * 272 + ch * 16);
            }
        }
        __syncthreads();
        if (i + 2 < 16) produce(i + 2);
    }

    // ---- row-sum reduction over quad columns ----
    sum0 += __shfl_xor_sync(0xffffffffu, sum0, 1);
    sum0 += __shfl_xor_sync(0xffffffffu, sum0, 2);
    sum1 += __shfl_xor_sync(0xffffffffu, sum1, 1);
    sum1 += __shfl_xor_sync(0xffffffffu, sum1, 2);
    const float inv0 = 1.0f / sum0, inv1 = 1.0f / sum1;
    if (lc == 0) {
        float* ip = invg + ((size_t)bh * 32 + rb) * 64;
        ip[row0]     = inv0;
        ip[row0 + 8] = inv1;
    }

    // ---- ctx epilogue: scale by inv, stage via PS, write fp16 ----
#pragma unroll
    for (int f8 = 0; f8 < 8; f8++) {
        __half2 c01 = __floats2half2_rn(ctxa[f8][0] * inv0, ctxa[f8][1] * inv0);
        __half2 c23 = __floats2half2_rn(ctxa[f8][2] * inv1, ctxa[f8][3] * inv1);
        *reinterpret_cast<uint32_t*>(sm + PS + row0 * 144 + f8 * 16 + lc * 4) =
            *reinterpret_cast<uint32_t*>(&c01);
        *reinterpret_cast<uint32_t*>(sm + PS + (row0 + 8) * 144 + f8 * 16 + lc * 4) =
            *reinterpret_cast<uint32_t*>(&c23);
    }
    __syncthreads();
    {
        __half* dst = ctx + ((size_t)b * S_ + (size_t)rb * 64) * D_ + h * 64;
        for (int c = tid; c < 512; c += 128) {
            int r = c >> 3, ch = c & 7;
            *reinterpret_cast<uint4*>(dst + (size_t)r * D_ + ch * 8) =
                *reinterpret_cast<uint4*>(sm + PS + r * 144 + ch * 16);
        }
    }
}

// ---------------- rescale p~ -> normalized fp32 attn (pure scale) ----------------
// blk = bh*32 + rb64; 16 tiles of 64x128 per blk.
__global__ __launch_bounds__(256) void attn_rescale(
    const __half* __restrict__ pscr, const float* __restrict__ invg,
    float* __restrict__ attn, int blk0)
{
    __shared__ float inv[64];
    const int blk = blk0 + blockIdx.x;
    const int by  = blockIdx.y;              // row half (32 rows each)
    const int bh = blk >> 5, rb = blk & 31;
    const int tid = threadIdx.x;
    if (tid < 64) inv[tid] = invg[(size_t)blk * 64 + tid];
    __syncthreads();
    const __half* src = pscr + ((size_t)blk << 17);
    float* dst = attn + ((size_t)bh * S_ + (size_t)rb * 64) * S_;
    const int ebase = by * 32 * 2048;
#pragma unroll 4
    for (int it = 0; it < 64; it++) {
        int e = ebase + (tid + it * 256) * 4;
        int r = e >> 11;
        int c = e & 2047;
        int t = c >> 7, tc = c & 127;
        uint2 pv = *reinterpret_cast<const uint2*>(src + ((size_t)t << 13) + r * 128 + tc);
        __half2 a  = *reinterpret_cast<__half2*>(&pv.x);
        __half2 b2 = *reinterpret_cast<__half2*>(&pv.y);
        float f = inv[r];
        float4 o;
        o.x = __half2float(a.x)  * f; o.y = __half2float(a.y)  * f;
        o.z = __half2float(b2.x) * f; o.w = __half2float(b2.y) * f;
        *reinterpret_cast<float4*>(dst + (size_t)r * S_ + c) = o;
    }
}

// ---------------- host ----------------
extern "C" void kernel_launch(void* const* d_in, const int* in_sizes, int n_in,
                              void* d_out, int out_size)
{
    const float* query = (const float*)d_in[0];
    const float* key   = (const float*)d_in[1];
    const float* value = (const float*)d_in[2];
    const float* Wq = (const float*)d_in[3];
    const float* bq = (const float*)d_in[4];
    const float* Wk = (const float*)d_in[5];
    const float* bk = (const float*)d_in[6];
    const float* Wv = (const float*)d_in[7];
    const float* bv = (const float*)d_in[8];
    const float* Wo = (const float*)d_in[9];
    const float* bo = (const float*)d_in[10];

    float* out  = (float*)d_out;
    float* attn = out + NELEM;

    __half *wt, *q16, *k16, *v16, *ctx, *ps;
    float* invb;
    cudaGetSymbolAddress((void**)&wt, g_wt);
    cudaGetSymbolAddress((void**)&q16, g_q16);
    cudaGetSymbolAddress((void**)&k16, g_k16);
    cudaGetSymbolAddress((void**)&v16, g_v16);
    cudaGetSymbolAddress((void**)&ctx, g_ctx);
    cudaGetSymbolAddress((void**)&ps, g_ps);
    cudaGetSymbolAddress((void**)&invb, g_inv);

    static cudaStream_t s2 = []() {
        cudaStream_t s; cudaStreamCreateWithFlags(&s, cudaStreamNonBlocking); return s;
    }();
    static cudaEvent_t evF0 = []() {
        cudaEvent_t e; cudaEventCreateWithFlags(&e, cudaEventDisableTiming); return e;
    }();
    static cudaEvent_t evF1 = []() {
        cudaEvent_t e; cudaEventCreateWithFlags(&e, cudaEventDisableTiming); return e;
    }();
    static cudaEvent_t evJoin = []() {
        cudaEvent_t e; cudaEventCreateWithFlags(&e, cudaEventDisableTiming); return e;
    }();

    auto GPQKV = gemm_proj<true,  true>;
    auto GPOUT = gemm_proj<false, false>;
    const int SM_PROJ = 4 * 128 * 80;   // 40960
    cudaFuncSetAttribute(GPQKV, cudaFuncAttributeMaxDynamicSharedMemorySize, SM_PROJ);
    cudaFuncSetAttribute(GPOUT, cudaFuncAttributeMaxDynamicSharedMemorySize, SM_PROJ);
    const int SM_ATTN = 91136;
    cudaFuncSetAttribute(attn_fused, cudaFuncAttributeMaxDynamicSharedMemorySize, SM_ATTN);

    // 1) transpose weights -> fp16 W^T
    wtrans_kernel<<<dim3(32, 32, 4), dim3(32, 8)>>>(Wq, Wk, Wv, Wo, wt);

    // 2) QKV projections (fused fp32->fp16 cast); Q folds 0.125*log2(e)
    gemm_proj<true, true><<<dim3(D_ / 128, (B_ * S_) / 128, 3), 256, SM_PROJ>>>(
        query, key, value, nullptr, wt, bq, bk, bv, nullptr, q16, k16, v16,
        0.125f * 1.4426950408889634f);

    // 3a) fused attention, bh half 0 (BM=64, 2 CTAs/SM)
    attn_fused<<<dim3(32, 16), 128, SM_ATTN>>>(q16, k16, v16, ps, invb, ctx, 0);
    cudaEventRecord(evF0, 0);

    // 3b) fused attention, bh half 1 (overlaps rescale half 0)
    attn_fused<<<dim3(32, 16), 128, SM_ATTN>>>(q16, k16, v16, ps, invb, ctx, 16);
    cudaEventRecord(evF1, 0);

    // 4a) rescale half 0 on s2, concurrent with fused half 1
    cudaStreamWaitEvent(s2, evF0, 0);
    attn_rescale<<<dim3(512, 2), 256, 0, s2>>>(ps, invb, attn, 0);

    // 4b) rescale half 1 on s2, concurrent with out projection
    cudaStreamWaitEvent(s2, evF1, 0);
    attn_rescale<<<dim3(512, 2), 256, 0, s2>>>(ps, invb, attn, 512);
    cudaEventRecord(evJoin, s2);

    // 5) out = ctx @ Wo + bo
    gemm_proj<false, false><<<dim3(D_ / 128, (B_ * S_) / 128, 1), 256, SM_PROJ>>>(
        nullptr, nullptr, nullptr, ctx, wt + 3 * D_ * D_, bo, nullptr, nullptr,
        out, nullptr, nullptr, nullptr, 1.0f);

    // join: main stream completion implies rescale done
    cudaStreamWaitEvent(0, evJoin, 0);
}